// round 13
// baseline (speedup 1.0000x reference)
#include <cuda_runtime.h>
#include <cuda_fp16.h>
#include <cstdint>

#define B_   128
#define N_   512
#define FIN  128
#define FOUT 64
#define L2E  1.4426950408889634f

// Scratch (allocation-free rule: __device__ globals)
__device__ __half g_hh[B_ * N_ * FOUT];   // h fp16, row-major [row][f]
__device__ float  g_s[B_ * N_];           // s * log2(e)
__device__ float  g_t[B_ * N_];           // t * log2(e)

// ---------------------------------------------------------------------------
// PTX helpers
// ---------------------------------------------------------------------------
__device__ __forceinline__ uint32_t smem_u32(const void* p) {
    return (uint32_t)__cvta_generic_to_shared(p);
}
__device__ __forceinline__ float ex2f(float x) {
    float y;
    asm("ex2.approx.f32 %0, %1;\n" : "=f"(y) : "f"(x));
    return y;
}
__device__ __forceinline__ void ldsm_x4(uint32_t& r0, uint32_t& r1, uint32_t& r2, uint32_t& r3, uint32_t addr) {
    asm volatile("ldmatrix.sync.aligned.m8n8.x4.shared.b16 {%0,%1,%2,%3}, [%4];\n"
                 : "=r"(r0), "=r"(r1), "=r"(r2), "=r"(r3) : "r"(addr));
}
__device__ __forceinline__ void ldsm_x4t(uint32_t& r0, uint32_t& r1, uint32_t& r2, uint32_t& r3, uint32_t addr) {
    asm volatile("ldmatrix.sync.aligned.m8n8.x4.trans.shared.b16 {%0,%1,%2,%3}, [%4];\n"
                 : "=r"(r0), "=r"(r1), "=r"(r2), "=r"(r3) : "r"(addr));
}
__device__ __forceinline__ void mma16816(float* d, const uint32_t* a, uint32_t b0, uint32_t b1) {
    asm volatile("mma.sync.aligned.m16n8k16.row.col.f32.f16.f16.f32 "
                 "{%0,%1,%2,%3},{%4,%5,%6,%7},{%8,%9},{%0,%1,%2,%3};\n"
                 : "+f"(d[0]), "+f"(d[1]), "+f"(d[2]), "+f"(d[3])
                 : "r"(a[0]), "r"(a[1]), "r"(a[2]), "r"(a[3]), "r"(b0), "r"(b1));
}
__device__ __forceinline__ void cp_async16(uint32_t saddr, const void* gptr) {
    asm volatile("cp.async.cg.shared.global [%0], [%1], 16;\n" :: "r"(saddr), "l"(gptr));
}
#define CP_COMMIT() asm volatile("cp.async.commit_group;\n" ::: "memory")
#define CP_WAIT0()  asm volatile("cp.async.wait_group 0;\n" ::: "memory")

// ---------------------------------------------------------------------------
// Kernel A: h = X @ W on tensor cores (fp16 3-term split).
// Epilogue: h fp16 store + fused s,t (scaled by log2e).  [proven, unchanged]
// ---------------------------------------------------------------------------
#define XS 72
#define WS 72

__global__ void __launch_bounds__(256, 3) gemm1_kernel(
    const float* __restrict__ X, const float* __restrict__ W,
    const float* __restrict__ a)
{
    extern __shared__ __half smh[];
    __half* Xhi = smh;                 // 128 x 72
    __half* Xlo = Xhi + 128 * XS;      // 128 x 72
    __half* Whi = Xlo + 128 * XS;      // 64 x 72
    __half* Wlo = Whi + 64 * WS;       // 64 x 72

    const int tid  = threadIdx.x;
    const int warp = tid >> 5;
    const int lane = tid & 31;
    const int m0   = blockIdx.x * 128;

    const int lrow16 = lane & 15;
    const int lhalf  = lane >> 4;
    const uint32_t aHi = smem_u32(Xhi + (warp * 16 + lrow16) * XS + lhalf * 8);
    const uint32_t aLo = smem_u32(Xlo + (warp * 16 + lrow16) * XS + lhalf * 8);
    const uint32_t bHi = smem_u32(Whi + lrow16 * WS + lhalf * 8);
    const uint32_t bLo = smem_u32(Wlo + lrow16 * WS + lhalf * 8);

    float acc[8][4] = {};

#pragma unroll
    for (int kh = 0; kh < 2; kh++) {
#pragma unroll
        for (int p = 0; p < 8; p++) {
            int u  = p * 256 + tid;
            int r  = u >> 4;
            int c4 = (u & 15) * 4;
            float4 xv = *(const float4*)(X + (size_t)(m0 + r) * FIN + kh * 64 + c4);
            __half h4[4], l4[4];
            h4[0] = __float2half(xv.x); l4[0] = __float2half(xv.x - __half2float(h4[0]));
            h4[1] = __float2half(xv.y); l4[1] = __float2half(xv.y - __half2float(h4[1]));
            h4[2] = __float2half(xv.z); l4[2] = __float2half(xv.z - __half2float(h4[2]));
            h4[3] = __float2half(xv.w); l4[3] = __float2half(xv.w - __half2float(h4[3]));
            *(uint2*)(Xhi + r * XS + c4) = *(uint2*)h4;
            *(uint2*)(Xlo + r * XS + c4) = *(uint2*)l4;
        }
#pragma unroll
        for (int p = 0; p < 4; p++) {
            int u  = p * 256 + tid;
            int k  = u >> 4;
            int c4 = (u & 15) * 4;
            float4 wv = *(const float4*)(W + (size_t)(kh * 64 + k) * FOUT + c4);
            __half h4[4], l4[4];
            h4[0] = __float2half(wv.x); l4[0] = __float2half(wv.x - __half2float(h4[0]));
            h4[1] = __float2half(wv.y); l4[1] = __float2half(wv.y - __half2float(h4[1]));
            h4[2] = __float2half(wv.z); l4[2] = __float2half(wv.z - __half2float(h4[2]));
            h4[3] = __float2half(wv.w); l4[3] = __float2half(wv.w - __half2float(h4[3]));
            *(uint2*)(Whi + k * WS + c4) = *(uint2*)h4;
            *(uint2*)(Wlo + k * WS + c4) = *(uint2*)l4;
        }
        __syncthreads();

#pragma unroll
        for (int ks = 0; ks < 4; ks++) {
            const uint32_t aOff = (uint32_t)(ks * 16) * 2;
            const uint32_t bOff = (uint32_t)(ks * 16) * WS * 2;
            uint32_t ah[4], al[4];
            ldsm_x4(ah[0], ah[1], ah[2], ah[3], aHi + aOff);
            ldsm_x4(al[0], al[1], al[2], al[3], aLo + aOff);
#pragma unroll
            for (int ng = 0; ng < 4; ng++) {
                uint32_t bh[4], bl[4];
                ldsm_x4t(bh[0], bh[1], bh[2], bh[3], bHi + bOff + ng * 32);
                ldsm_x4t(bl[0], bl[1], bl[2], bl[3], bLo + bOff + ng * 32);
                mma16816(acc[ng * 2],     ah, bh[0], bh[1]);
                mma16816(acc[ng * 2],     ah, bl[0], bl[1]);
                mma16816(acc[ng * 2],     al, bh[0], bh[1]);
                mma16816(acc[ng * 2 + 1], ah, bh[2], bh[3]);
                mma16816(acc[ng * 2 + 1], ah, bl[2], bl[3]);
                mma16816(acc[ng * 2 + 1], al, bh[2], bh[3]);
            }
        }
        __syncthreads();
    }

    const int gid = lane >> 2;
    const int tg  = lane & 3;
    const size_t rA = (size_t)m0 + warp * 16 + gid;
    const size_t rB = rA + 8;

    float spA = 0.f, tpA = 0.f, spB = 0.f, tpB = 0.f;
#pragma unroll
    for (int j = 0; j < 8; j++) {
        int col = j * 8 + tg * 2;
        float a0 = __ldg(a + col), a1 = __ldg(a + col + 1);
        float d0 = __ldg(a + 64 + col), d1 = __ldg(a + 64 + col + 1);

        __half2 hA = __floats2half2_rn(acc[j][0], acc[j][1]);
        __half2 hB = __floats2half2_rn(acc[j][2], acc[j][3]);
        *(uint32_t*)(g_hh + rA * FOUT + col) = *(uint32_t*)&hA;
        *(uint32_t*)(g_hh + rB * FOUT + col) = *(uint32_t*)&hB;

        spA += acc[j][0] * a0 + acc[j][1] * a1;
        tpA += acc[j][0] * d0 + acc[j][1] * d1;
        spB += acc[j][2] * a0 + acc[j][3] * a1;
        tpB += acc[j][2] * d0 + acc[j][3] * d1;
    }
#pragma unroll
    for (int o = 1; o <= 2; o <<= 1) {
        spA += __shfl_xor_sync(0xffffffffu, spA, o);
        tpA += __shfl_xor_sync(0xffffffffu, tpA, o);
        spB += __shfl_xor_sync(0xffffffffu, spB, o);
        tpB += __shfl_xor_sync(0xffffffffu, tpB, o);
    }
    if (tg == 0) {
        g_s[rA] = spA * L2E; g_t[rA] = tpA * L2E;
        g_s[rB] = spB * L2E; g_t[rB] = tpB * L2E;
    }
}

// ---------------------------------------------------------------------------
// Kernel B: chunked masked-softmax + tensor-core att@h.  [72.2µs kernel]
// ONLY delta this round: __launch_bounds__(256, 5) — regs forced <=51 to
// lift register-capped occupancy from 4 to 5 blocks/SM. Code unchanged.
// ---------------------------------------------------------------------------
#define ATT_S 72
#define HS_S  72

__global__ void __launch_bounds__(256, 5) attn_kernel(
    const int* __restrict__ adj, float* __restrict__ out)
{
    extern __shared__ char smraw[];
    float2* t2_sh = (float2*)smraw;              // 512 x (t, 0.2t)  [log2 domain]
    float* inv  = (float*)(t2_sh + 512);         // 32
    float* wmax = inv + 32;                      // 8
    __half* attC = (__half*)(wmax + 8);          // 2 x 32 x 72
    __half* hsC  = attC + 2 * 32 * ATT_S;        // 2 x 64 x 72

    const int b    = blockIdx.y;
    const int r0   = blockIdx.x * 32;
    const int tid  = threadIdx.x;
    const int warp = tid >> 5;
    const int lane = tid & 31;

    const int ld_row = tid >> 3;
    const int ld_off = (tid & 7) * 8;
    const __half* hb = g_hh + (size_t)b * N_ * FOUT;
    const uint32_t hsBase = smem_u32(hsC);

    // prologue: stream hs chunk 0 into buf 0
    cp_async16(hsBase + (uint32_t)((ld_row)      * HS_S + ld_off) * 2, hb + (size_t)(ld_row)      * FOUT + ld_off);
    cp_async16(hsBase + (uint32_t)((ld_row + 32) * HS_S + ld_off) * 2, hb + (size_t)(ld_row + 32) * FOUT + ld_off);
    CP_COMMIT();

    float t0 = g_t[b * N_ + tid];
    float t1 = g_t[b * N_ + tid + 256];
    t2_sh[tid]       = make_float2(t0, 0.2f * t0);
    t2_sh[tid + 256] = make_float2(t1, 0.2f * t1);

    float m2 = fmaxf(t0, t1);
#pragma unroll
    for (int o = 16; o; o >>= 1) m2 = fmaxf(m2, __shfl_xor_sync(0xffffffffu, m2, o));
    if (lane == 0) wmax[warp] = m2;
    __syncthreads();
    const float maxT = fmaxf(fmaxf(fmaxf(wmax[0], wmax[1]), fmaxf(wmax[2], wmax[3])),
                             fmaxf(fmaxf(wmax[4], wmax[5]), fmaxf(wmax[6], wmax[7])));

    // per-row constants (warp owns local rows warp*4 .. +3), shift pre-folded
    float s1_r[4], s2_r[4], sum_r[4];
#pragma unroll
    for (int rr = 0; rr < 4; rr++) {
        int grow = r0 + warp * 4 + rr;
        float s  = g_s[b * N_ + grow];
        float pm = s + maxT;
        float mx = fmaxf(pm, 0.2f * pm);   // log2-domain row max (leaky homogeneous)
        s1_r[rr] = s - mx;
        s2_r[rr] = 0.2f * s - mx;
        sum_r[rr] = 0.f;
    }

    const int mtile  = warp >> 2;
    const int ntg0   = (warp & 3) * 2;
    const int lrow16 = lane & 15;
    const int lhalf  = lane >> 4;
    const uint32_t aBase = smem_u32(attC + (mtile * 16 + lrow16) * ATT_S + lhalf * 8);
    const uint32_t bBase = smem_u32(hsC + lrow16 * HS_S + (ntg0 + lhalf) * 8);
    const uint32_t attBufB = (uint32_t)(32 * ATT_S) * 2;
    const uint32_t hsBufB  = (uint32_t)(64 * HS_S) * 2;

    float acc0[4] = {0.f, 0.f, 0.f, 0.f};
    float acc1[4] = {0.f, 0.f, 0.f, 0.f};

    const int* adjB = adj + ((size_t)b * N_ + r0) * N_;

    // adj prefetch for chunk 0
    int2 avc[4], avn[4];
#pragma unroll
    for (int rr = 0; rr < 4; rr++)
        avc[rr] = *(const int2*)(adjB + (size_t)(warp * 4 + rr) * N_ + lane * 2);

    for (int c = 0; c < 8; c++) {
        const int k0  = c * 64;
        const int buf = c & 1;

        // issue adj prefetch for chunk c+1
        if (c < 7) {
#pragma unroll
            for (int rr = 0; rr < 4; rr++)
                avn[rr] = *(const int2*)(adjB + (size_t)(warp * 4 + rr) * N_ + k0 + 64 + lane * 2);
        }

        // phase-1: weights for 32 rows x 64 cols -> attC[buf]
        // q = (t_j, 0.2 t_j, t_{j+1}, 0.2 t_{j+1}) — row-independent, loaded once
        __half* attW = attC + buf * 32 * ATT_S;
        const float4 q = *(const float4*)(t2_sh + k0 + lane * 2);
#pragma unroll
        for (int rr = 0; rr < 4; rr++) {
            int r = warp * 4 + rr;
            float a0 = fmaxf(s1_r[rr] + q.x, s2_r[rr] + q.y);
            float a1 = fmaxf(s1_r[rr] + q.z, s2_r[rr] + q.w);
            float w0 = avc[rr].x > 0 ? ex2f(a0) : 0.f;
            float w1 = avc[rr].y > 0 ? ex2f(a1) : 0.f;
            sum_r[rr] += w0 + w1;
            __half2 p = __floats2half2_rn(w0, w1);
            *(uint32_t*)(attW + r * ATT_S + lane * 2) = *(uint32_t*)&p;
        }

        CP_WAIT0();            // hs[c] landed
        __syncthreads();       // attC[buf] + hs[buf] visible

        // stream hs chunk c+1 into the other buffer
        if (c < 7) {
            const __half* hn = hb + (size_t)(k0 + 64) * FOUT;
            uint32_t dst = hsBase + (1 - buf) * hsBufB;
            cp_async16(dst + (uint32_t)((ld_row)      * HS_S + ld_off) * 2, hn + (size_t)(ld_row)      * FOUT + ld_off);
            cp_async16(dst + (uint32_t)((ld_row + 32) * HS_S + ld_off) * 2, hn + (size_t)(ld_row + 32) * FOUT + ld_off);
            CP_COMMIT();
        }

        // MMA: C[32,64] += attC[buf] @ hsC[buf]
        const uint32_t aA = aBase + buf * attBufB;
        const uint32_t bA = bBase + buf * hsBufB;
#pragma unroll
        for (int ks = 0; ks < 4; ks++) {
            const uint32_t aOff = (uint32_t)(ks * 16) * 2;
            const uint32_t bOff = (uint32_t)(ks * 16) * HS_S * 2;
            uint32_t av[4], b0, b1, b2, b3;
            ldsm_x4(av[0], av[1], av[2], av[3], aA + aOff);
            ldsm_x4t(b0, b1, b2, b3, bA + bOff);
            mma16816(acc0, av, b0, b1);
            mma16816(acc1, av, b2, b3);
        }

#pragma unroll
        for (int rr = 0; rr < 4; rr++) avc[rr] = avn[rr];
    }

    // row sums -> inv
#pragma unroll
    for (int rr = 0; rr < 4; rr++) {
        float sum = sum_r[rr];
#pragma unroll
        for (int o = 16; o; o >>= 1) sum += __shfl_xor_sync(0xffffffffu, sum, o);
        if (lane == 0) inv[warp * 4 + rr] = 1.0f / sum;
    }
    __syncthreads();

    // epilogue: normalize + leaky_relu(0.01) + store
    const int gid = lane >> 2;
    const int tg  = lane & 3;
    const int rA  = mtile * 16 + gid;
    const int rB  = rA + 8;
    const float invA = inv[rA];
    const float invB = inv[rB];

#pragma unroll
    for (int nt = 0; nt < 2; nt++) {
        float* acc = nt ? acc1 : acc0;
        int col = (ntg0 + nt) * 8 + tg * 2;
        float v;
        float2 oA, oB;
        v = acc[0] * invA; oA.x = v > 0.f ? v : 0.01f * v;
        v = acc[1] * invA; oA.y = v > 0.f ? v : 0.01f * v;
        v = acc[2] * invB; oB.x = v > 0.f ? v : 0.01f * v;
        v = acc[3] * invB; oB.y = v > 0.f ? v : 0.01f * v;
        *(float2*)(out + ((size_t)b * N_ + r0 + rA) * FOUT + col) = oA;
        *(float2*)(out + ((size_t)b * N_ + r0 + rB) * FOUT + col) = oB;
    }
}

// ---------------------------------------------------------------------------
extern "C" void kernel_launch(void* const* d_in, const int* in_sizes, int n_in,
                              void* d_out, int out_size)
{
    const float* X   = (const float*)d_in[0];
    const int*   adj = (const int*)  d_in[1];
    const float* W   = (const float*)d_in[2];
    const float* a   = (const float*)d_in[3];
    float* out = (float*)d_out;

    size_t smA = (size_t)(2 * 128 * XS + 2 * 64 * WS) * sizeof(__half);   // 55.3 KB
    cudaFuncSetAttribute(gemm1_kernel, cudaFuncAttributeMaxDynamicSharedMemorySize, (int)smA);
    gemm1_kernel<<<(B_ * N_) / 128, 256, smA>>>(X, W, a);

    size_t smB = 512 * sizeof(float2) + (32 + 8) * sizeof(float)
               + (size_t)(2 * 32 * ATT_S + 2 * 64 * HS_S) * sizeof(__half);  // ~31.2 KB
    cudaFuncSetAttribute(attn_kernel, cudaFuncAttributeMaxDynamicSharedMemorySize, (int)smB);
    attn_kernel<<<dim3(N_ / 32, B_), 256, smB>>>(adj, out);
}

// round 14
// speedup vs baseline: 1.5800x; 1.5800x over previous
#include <cuda_runtime.h>
#include <cuda_fp16.h>
#include <cstdint>

#define B_   128
#define N_   512
#define FIN  128
#define FOUT 64
#define L2E  1.4426950408889634f

// Scratch (allocation-free rule: __device__ globals)
__device__ __half g_hh[B_ * N_ * FOUT];   // h fp16, row-major [row][f]
__device__ float  g_s[B_ * N_];           // s * log2(e)
__device__ float  g_t[B_ * N_];           // t * log2(e)

// ---------------------------------------------------------------------------
// PTX helpers
// ---------------------------------------------------------------------------
__device__ __forceinline__ uint32_t smem_u32(const void* p) {
    return (uint32_t)__cvta_generic_to_shared(p);
}
__device__ __forceinline__ float ex2f(float x) {
    float y;
    asm("ex2.approx.f32 %0, %1;\n" : "=f"(y) : "f"(x));
    return y;
}
__device__ __forceinline__ void ldsm_x4(uint32_t& r0, uint32_t& r1, uint32_t& r2, uint32_t& r3, uint32_t addr) {
    asm volatile("ldmatrix.sync.aligned.m8n8.x4.shared.b16 {%0,%1,%2,%3}, [%4];\n"
                 : "=r"(r0), "=r"(r1), "=r"(r2), "=r"(r3) : "r"(addr));
}
__device__ __forceinline__ void ldsm_x4t(uint32_t& r0, uint32_t& r1, uint32_t& r2, uint32_t& r3, uint32_t addr) {
    asm volatile("ldmatrix.sync.aligned.m8n8.x4.trans.shared.b16 {%0,%1,%2,%3}, [%4];\n"
                 : "=r"(r0), "=r"(r1), "=r"(r2), "=r"(r3) : "r"(addr));
}
__device__ __forceinline__ void mma16816(float* d, const uint32_t* a, uint32_t b0, uint32_t b1) {
    asm volatile("mma.sync.aligned.m16n8k16.row.col.f32.f16.f16.f32 "
                 "{%0,%1,%2,%3},{%4,%5,%6,%7},{%8,%9},{%0,%1,%2,%3};\n"
                 : "+f"(d[0]), "+f"(d[1]), "+f"(d[2]), "+f"(d[3])
                 : "r"(a[0]), "r"(a[1]), "r"(a[2]), "r"(a[3]), "r"(b0), "r"(b1));
}
__device__ __forceinline__ void cp_async16(uint32_t saddr, const void* gptr) {
    asm volatile("cp.async.cg.shared.global [%0], [%1], 16;\n" :: "r"(saddr), "l"(gptr));
}
#define CP_COMMIT() asm volatile("cp.async.commit_group;\n" ::: "memory")
#define CP_WAIT0()  asm volatile("cp.async.wait_group 0;\n" ::: "memory")

// ---------------------------------------------------------------------------
// Kernel A: h = X @ W on tensor cores (fp16 3-term split), M_TILE = 256.
// Grid = 256 blocks @ 2 blocks/SM -> SINGLE WAVE (was 512 @ 3/SM = 2 waves).
// Each warp owns 2 m16 tiles (rows 32w .. 32w+31). Epilogue unchanged math.
// ---------------------------------------------------------------------------
#define MT  256
#define XS  72
#define WS  72

__global__ void __launch_bounds__(256, 2) gemm1_kernel(
    const float* __restrict__ X, const float* __restrict__ W,
    const float* __restrict__ a)
{
    extern __shared__ __half smh[];
    __half* Xhi = smh;                 // 256 x 72
    __half* Xlo = Xhi + MT * XS;       // 256 x 72
    __half* Whi = Xlo + MT * XS;       // 64 x 72
    __half* Wlo = Whi + 64 * WS;       // 64 x 72

    const int tid  = threadIdx.x;
    const int warp = tid >> 5;
    const int lane = tid & 31;
    const int m0   = blockIdx.x * MT;

    const int lrow16 = lane & 15;
    const int lhalf  = lane >> 4;
    // A fragment bases for this warp's two m16 tiles
    const uint32_t aHi0 = smem_u32(Xhi + (warp * 32 + lrow16) * XS + lhalf * 8);
    const uint32_t aLo0 = smem_u32(Xlo + (warp * 32 + lrow16) * XS + lhalf * 8);
    const uint32_t mtOff = (uint32_t)(16 * XS) * 2;   // bytes between m16 tiles
    const uint32_t bHiB = smem_u32(Whi + lrow16 * WS + lhalf * 8);
    const uint32_t bLoB = smem_u32(Wlo + lrow16 * WS + lhalf * 8);

    float acc[16][4] = {};   // [mt*8 + ng*2 + nt][4]

#pragma unroll
    for (int kh = 0; kh < 2; kh++) {
        // X half-tile 256x64 fp32 -> hi/lo fp16 (16 float4 per thread)
#pragma unroll
        for (int p = 0; p < 16; p++) {
            int u  = p * 256 + tid;
            int r  = u >> 4;
            int c4 = (u & 15) * 4;
            float4 xv = *(const float4*)(X + (size_t)(m0 + r) * FIN + kh * 64 + c4);
            __half h4[4], l4[4];
            h4[0] = __float2half(xv.x); l4[0] = __float2half(xv.x - __half2float(h4[0]));
            h4[1] = __float2half(xv.y); l4[1] = __float2half(xv.y - __half2float(h4[1]));
            h4[2] = __float2half(xv.z); l4[2] = __float2half(xv.z - __half2float(h4[2]));
            h4[3] = __float2half(xv.w); l4[3] = __float2half(xv.w - __half2float(h4[3]));
            *(uint2*)(Xhi + r * XS + c4) = *(uint2*)h4;
            *(uint2*)(Xlo + r * XS + c4) = *(uint2*)l4;
        }
        // W half 64x64 -> hi/lo fp16
#pragma unroll
        for (int p = 0; p < 4; p++) {
            int u  = p * 256 + tid;
            int k  = u >> 4;
            int c4 = (u & 15) * 4;
            float4 wv = *(const float4*)(W + (size_t)(kh * 64 + k) * FOUT + c4);
            __half h4[4], l4[4];
            h4[0] = __float2half(wv.x); l4[0] = __float2half(wv.x - __half2float(h4[0]));
            h4[1] = __float2half(wv.y); l4[1] = __float2half(wv.y - __half2float(h4[1]));
            h4[2] = __float2half(wv.z); l4[2] = __float2half(wv.z - __half2float(h4[2]));
            h4[3] = __float2half(wv.w); l4[3] = __float2half(wv.w - __half2float(h4[3]));
            *(uint2*)(Whi + k * WS + c4) = *(uint2*)h4;
            *(uint2*)(Wlo + k * WS + c4) = *(uint2*)l4;
        }
        __syncthreads();

#pragma unroll
        for (int ks = 0; ks < 4; ks++) {
            const uint32_t aOff = (uint32_t)(ks * 16) * 2;
            const uint32_t bOff = (uint32_t)(ks * 16) * WS * 2;
            // A fragments for both m16 tiles (hi and lo)
            uint32_t ah0[4], al0[4], ah1[4], al1[4];
            ldsm_x4(ah0[0], ah0[1], ah0[2], ah0[3], aHi0 + aOff);
            ldsm_x4(al0[0], al0[1], al0[2], al0[3], aLo0 + aOff);
            ldsm_x4(ah1[0], ah1[1], ah1[2], ah1[3], aHi0 + mtOff + aOff);
            ldsm_x4(al1[0], al1[1], al1[2], al1[3], aLo0 + mtOff + aOff);
#pragma unroll
            for (int ng = 0; ng < 4; ng++) {
                uint32_t bh[4], bl[4];
                ldsm_x4t(bh[0], bh[1], bh[2], bh[3], bHiB + bOff + ng * 32);
                ldsm_x4t(bl[0], bl[1], bl[2], bl[3], bLoB + bOff + ng * 32);
                // mt = 0
                mma16816(acc[ng * 2],     ah0, bh[0], bh[1]);
                mma16816(acc[ng * 2],     ah0, bl[0], bl[1]);
                mma16816(acc[ng * 2],     al0, bh[0], bh[1]);
                mma16816(acc[ng * 2 + 1], ah0, bh[2], bh[3]);
                mma16816(acc[ng * 2 + 1], ah0, bl[2], bl[3]);
                mma16816(acc[ng * 2 + 1], al0, bh[2], bh[3]);
                // mt = 1
                mma16816(acc[8 + ng * 2],     ah1, bh[0], bh[1]);
                mma16816(acc[8 + ng * 2],     ah1, bl[0], bl[1]);
                mma16816(acc[8 + ng * 2],     al1, bh[0], bh[1]);
                mma16816(acc[8 + ng * 2 + 1], ah1, bh[2], bh[3]);
                mma16816(acc[8 + ng * 2 + 1], ah1, bl[2], bl[3]);
                mma16816(acc[8 + ng * 2 + 1], al1, bh[2], bh[3]);
            }
        }
        __syncthreads();
    }

    // Epilogue per m16 tile: h fp16 store + fused s/t (log2 domain)
    const int gid = lane >> 2;
    const int tg  = lane & 3;
#pragma unroll
    for (int mt = 0; mt < 2; mt++) {
        const size_t rA = (size_t)m0 + warp * 32 + mt * 16 + gid;
        const size_t rB = rA + 8;
        float spA = 0.f, tpA = 0.f, spB = 0.f, tpB = 0.f;
#pragma unroll
        for (int j = 0; j < 8; j++) {
            int col = j * 8 + tg * 2;
            float a0 = __ldg(a + col), a1 = __ldg(a + col + 1);
            float d0 = __ldg(a + 64 + col), d1 = __ldg(a + 64 + col + 1);
            float* ac = acc[mt * 8 + j];

            __half2 hA = __floats2half2_rn(ac[0], ac[1]);
            __half2 hB = __floats2half2_rn(ac[2], ac[3]);
            *(uint32_t*)(g_hh + rA * FOUT + col) = *(uint32_t*)&hA;
            *(uint32_t*)(g_hh + rB * FOUT + col) = *(uint32_t*)&hB;

            spA += ac[0] * a0 + ac[1] * a1;
            tpA += ac[0] * d0 + ac[1] * d1;
            spB += ac[2] * a0 + ac[3] * a1;
            tpB += ac[2] * d0 + ac[3] * d1;
        }
#pragma unroll
        for (int o = 1; o <= 2; o <<= 1) {
            spA += __shfl_xor_sync(0xffffffffu, spA, o);
            tpA += __shfl_xor_sync(0xffffffffu, tpA, o);
            spB += __shfl_xor_sync(0xffffffffu, spB, o);
            tpB += __shfl_xor_sync(0xffffffffu, tpB, o);
        }
        if (tg == 0) {
            g_s[rA] = spA * L2E; g_t[rA] = tpA * L2E;
            g_s[rB] = spB * L2E; g_t[rB] = tpB * L2E;
        }
    }
}

// ---------------------------------------------------------------------------
// Kernel B: chunked masked-softmax + tensor-core att@h.
// EXACT revert to the proven 46.5µs R12 kernel (launch_bounds (256,4)).
// ---------------------------------------------------------------------------
#define ATT_S 72
#define HS_S  72

__global__ void __launch_bounds__(256, 4) attn_kernel(
    const int* __restrict__ adj, float* __restrict__ out)
{
    extern __shared__ char smraw[];
    float2* t2_sh = (float2*)smraw;              // 512 x (t, 0.2t)  [log2 domain]
    float* inv  = (float*)(t2_sh + 512);         // 32
    float* wmax = inv + 32;                      // 8
    __half* attC = (__half*)(wmax + 8);          // 2 x 32 x 72
    __half* hsC  = attC + 2 * 32 * ATT_S;        // 2 x 64 x 72

    const int b    = blockIdx.y;
    const int r0   = blockIdx.x * 32;
    const int tid  = threadIdx.x;
    const int warp = tid >> 5;
    const int lane = tid & 31;

    const int ld_row = tid >> 3;
    const int ld_off = (tid & 7) * 8;
    const __half* hb = g_hh + (size_t)b * N_ * FOUT;
    const uint32_t hsBase = smem_u32(hsC);

    // prologue: stream hs chunk 0 into buf 0
    cp_async16(hsBase + (uint32_t)((ld_row)      * HS_S + ld_off) * 2, hb + (size_t)(ld_row)      * FOUT + ld_off);
    cp_async16(hsBase + (uint32_t)((ld_row + 32) * HS_S + ld_off) * 2, hb + (size_t)(ld_row + 32) * FOUT + ld_off);
    CP_COMMIT();

    float t0 = g_t[b * N_ + tid];
    float t1 = g_t[b * N_ + tid + 256];
    t2_sh[tid]       = make_float2(t0, 0.2f * t0);
    t2_sh[tid + 256] = make_float2(t1, 0.2f * t1);

    float m2 = fmaxf(t0, t1);
#pragma unroll
    for (int o = 16; o; o >>= 1) m2 = fmaxf(m2, __shfl_xor_sync(0xffffffffu, m2, o));
    if (lane == 0) wmax[warp] = m2;
    __syncthreads();
    const float maxT = fmaxf(fmaxf(fmaxf(wmax[0], wmax[1]), fmaxf(wmax[2], wmax[3])),
                             fmaxf(fmaxf(wmax[4], wmax[5]), fmaxf(wmax[6], wmax[7])));

    // per-row constants (warp owns local rows warp*4 .. +3), shift pre-folded
    float s1_r[4], s2_r[4], sum_r[4];
#pragma unroll
    for (int rr = 0; rr < 4; rr++) {
        int grow = r0 + warp * 4 + rr;
        float s  = g_s[b * N_ + grow];
        float pm = s + maxT;
        float mx = fmaxf(pm, 0.2f * pm);   // log2-domain row max (leaky homogeneous)
        s1_r[rr] = s - mx;
        s2_r[rr] = 0.2f * s - mx;
        sum_r[rr] = 0.f;
    }

    const int mtile  = warp >> 2;
    const int ntg0   = (warp & 3) * 2;
    const int lrow16 = lane & 15;
    const int lhalf  = lane >> 4;
    const uint32_t aBase = smem_u32(attC + (mtile * 16 + lrow16) * ATT_S + lhalf * 8);
    const uint32_t bBase = smem_u32(hsC + lrow16 * HS_S + (ntg0 + lhalf) * 8);
    const uint32_t attBufB = (uint32_t)(32 * ATT_S) * 2;
    const uint32_t hsBufB  = (uint32_t)(64 * HS_S) * 2;

    float acc0[4] = {0.f, 0.f, 0.f, 0.f};
    float acc1[4] = {0.f, 0.f, 0.f, 0.f};

    const int* adjB = adj + ((size_t)b * N_ + r0) * N_;

    // adj prefetch for chunk 0
    int2 avc[4], avn[4];
#pragma unroll
    for (int rr = 0; rr < 4; rr++)
        avc[rr] = *(const int2*)(adjB + (size_t)(warp * 4 + rr) * N_ + lane * 2);

    for (int c = 0; c < 8; c++) {
        const int k0  = c * 64;
        const int buf = c & 1;

        // issue adj prefetch for chunk c+1
        if (c < 7) {
#pragma unroll
            for (int rr = 0; rr < 4; rr++)
                avn[rr] = *(const int2*)(adjB + (size_t)(warp * 4 + rr) * N_ + k0 + 64 + lane * 2);
        }

        // phase-1: weights for 32 rows x 64 cols -> attC[buf]
        __half* attW = attC + buf * 32 * ATT_S;
        const float4 q = *(const float4*)(t2_sh + k0 + lane * 2);
#pragma unroll
        for (int rr = 0; rr < 4; rr++) {
            int r = warp * 4 + rr;
            float a0 = fmaxf(s1_r[rr] + q.x, s2_r[rr] + q.y);
            float a1 = fmaxf(s1_r[rr] + q.z, s2_r[rr] + q.w);
            float w0 = avc[rr].x > 0 ? ex2f(a0) : 0.f;
            float w1 = avc[rr].y > 0 ? ex2f(a1) : 0.f;
            sum_r[rr] += w0 + w1;
            __half2 p = __floats2half2_rn(w0, w1);
            *(uint32_t*)(attW + r * ATT_S + lane * 2) = *(uint32_t*)&p;
        }

        CP_WAIT0();            // hs[c] landed
        __syncthreads();       // attC[buf] + hs[buf] visible

        // stream hs chunk c+1 into the other buffer
        if (c < 7) {
            const __half* hn = hb + (size_t)(k0 + 64) * FOUT;
            uint32_t dst = hsBase + (1 - buf) * hsBufB;
            cp_async16(dst + (uint32_t)((ld_row)      * HS_S + ld_off) * 2, hn + (size_t)(ld_row)      * FOUT + ld_off);
            cp_async16(dst + (uint32_t)((ld_row + 32) * HS_S + ld_off) * 2, hn + (size_t)(ld_row + 32) * FOUT + ld_off);
            CP_COMMIT();
        }

        // MMA: C[32,64] += attC[buf] @ hsC[buf]
        const uint32_t aA = aBase + buf * attBufB;
        const uint32_t bA = bBase + buf * hsBufB;
#pragma unroll
        for (int ks = 0; ks < 4; ks++) {
            const uint32_t aOff = (uint32_t)(ks * 16) * 2;
            const uint32_t bOff = (uint32_t)(ks * 16) * HS_S * 2;
            uint32_t av[4], b0, b1, b2, b3;
            ldsm_x4(av[0], av[1], av[2], av[3], aA + aOff);
            ldsm_x4t(b0, b1, b2, b3, bA + bOff);
            mma16816(acc0, av, b0, b1);
            mma16816(acc1, av, b2, b3);
        }

#pragma unroll
        for (int rr = 0; rr < 4; rr++) avc[rr] = avn[rr];
    }

    // row sums -> inv
#pragma unroll
    for (int rr = 0; rr < 4; rr++) {
        float sum = sum_r[rr];
#pragma unroll
        for (int o = 16; o; o >>= 1) sum += __shfl_xor_sync(0xffffffffu, sum, o);
        if (lane == 0) inv[warp * 4 + rr] = 1.0f / sum;
    }
    __syncthreads();

    // epilogue: normalize + leaky_relu(0.01) + store
    const int gid = lane >> 2;
    const int tg  = lane & 3;
    const int rA  = mtile * 16 + gid;
    const int rB  = rA + 8;
    const float invA = inv[rA];
    const float invB = inv[rB];

#pragma unroll
    for (int nt = 0; nt < 2; nt++) {
        float* acc = nt ? acc1 : acc0;
        int col = (ntg0 + nt) * 8 + tg * 2;
        float v;
        float2 oA, oB;
        v = acc[0] * invA; oA.x = v > 0.f ? v : 0.01f * v;
        v = acc[1] * invA; oA.y = v > 0.f ? v : 0.01f * v;
        v = acc[2] * invB; oB.x = v > 0.f ? v : 0.01f * v;
        v = acc[3] * invB; oB.y = v > 0.f ? v : 0.01f * v;
        *(float2*)(out + ((size_t)b * N_ + r0 + rA) * FOUT + col) = oA;
        *(float2*)(out + ((size_t)b * N_ + r0 + rB) * FOUT + col) = oB;
    }
}

// ---------------------------------------------------------------------------
extern "C" void kernel_launch(void* const* d_in, const int* in_sizes, int n_in,
                              void* d_out, int out_size)
{
    const float* X   = (const float*)d_in[0];
    const int*   adj = (const int*)  d_in[1];
    const float* W   = (const float*)d_in[2];
    const float* a   = (const float*)d_in[3];
    float* out = (float*)d_out;

    size_t smA = (size_t)(2 * MT * XS + 2 * 64 * WS) * sizeof(__half);   // 90 KB
    cudaFuncSetAttribute(gemm1_kernel, cudaFuncAttributeMaxDynamicSharedMemorySize, (int)smA);
    gemm1_kernel<<<(B_ * N_) / MT, 256, smA>>>(X, W, a);

    size_t smB = 512 * sizeof(float2) + (32 + 8) * sizeof(float)
               + (size_t)(2 * 32 * ATT_S + 2 * 64 * HS_S) * sizeof(__half);  // ~31.2 KB
    cudaFuncSetAttribute(attn_kernel, cudaFuncAttributeMaxDynamicSharedMemorySize, (int)smB);
    attn_kernel<<<dim3(N_ / 32, B_), 256, smB>>>(adj, out);
}